// round 3
// baseline (speedup 1.0000x reference)
#include <cuda_runtime.h>

#define Bb 8
#define Tt 800
#define Cc 8
#define Ff 513
#define Aa 320
#define NSYS (Bb*Ff)
#define CH 80                 // t-chunk
#define NCH (Tt/CH)           // 10
#define ROWP 9                // padded row: 8 c + 1 pad (float2) = 72B
#define TILE_F2 (8*CH*ROWP)   // 5760 float2 per tile buffer
#define MASK_F2 (8*Tt)        // 6400 float2
#define DYN_SMEM ((MASK_F2 + 2*TILE_F2)*8)   // 143360 B

// ---------------- device scratch ----------------
__device__ float2 g_psd_s[NSYS*64];
__device__ float2 g_psd_n[NSYS*64];
__device__ float  g_e[Bb*Cc];
__device__ float  g_part[64*9*Aa];
__device__ float2 g_wsc[Bb*Cc*Ff];   // conj(ws), layout (b, c, f)

typedef unsigned long long u64;

__device__ __forceinline__ u64 pk2(float lo, float hi){
    u64 r; asm("mov.b64 %0, {%1, %2};" : "=l"(r) : "f"(lo), "f"(hi)); return r;
}
__device__ __forceinline__ void upk2(float &lo, float &hi, u64 v){
    asm("mov.b64 {%0, %1}, %2;" : "=f"(lo), "=f"(hi) : "l"(v));
}
__device__ __forceinline__ void fma2(u64 &d, u64 a, u64 b){
    asm("fma.rn.f32x2 %0, %1, %2, %0;" : "+l"(d) : "l"(a), "l"(b));
}
__device__ __forceinline__ u64 add2(u64 a, u64 b){
    u64 r; asm("add.rn.f32x2 %0, %1, %2;" : "=l"(r) : "l"(a), "l"(b)); return r;
}
__device__ __forceinline__ unsigned s2u(const void* p){
    return (unsigned)__cvta_generic_to_shared(p);
}
__device__ __forceinline__ void cpa4(unsigned dst, const float* src){
    asm volatile("cp.async.ca.shared.global [%0], [%1], 4;" :: "r"(dst), "l"(src));
}
__device__ __forceinline__ void cpa_commit(){ asm volatile("cp.async.commit_group;"); }

__device__ __forceinline__ float2 cmul(float2 a, float2 b){
    return make_float2(a.x*b.x - a.y*b.y, a.x*b.y + a.y*b.x);
}
__device__ __forceinline__ float2 csub(float2 a, float2 b){
    return make_float2(a.x - b.x, a.y - b.y);
}
__device__ __forceinline__ float2 cinv(float2 a){
    float d = 1.f/(a.x*a.x + a.y*a.y);
    return make_float2(a.x*d, -a.y*d);
}

// ---------------- K1: PSD (speech + noise) -------------------------------
// grid (65, 8), block 256
__global__ void __launch_bounds__(256) psd_kernel(
    const float* __restrict__ dre,
    const float* __restrict__ dimg,
    const float* __restrict__ msk_s,
    const float* __restrict__ msk_n)
{
    extern __shared__ float2 sm2[];
    float2* smm   = sm2;               // [8][800] (ms, mn)
    float2* tileA = sm2 + MASK_F2;     // [8][CH][ROWP]
    float2* tileB = tileA + TILE_F2;
    __shared__ float inv_s[8], inv_n[8];

    const int tid  = threadIdx.x;
    const int b    = blockIdx.y;
    const int f0   = blockIdx.x * 8;
    const int warp = tid >> 5;
    const int lane = tid & 31;

    const size_t bbase = (size_t)b * Tt * Cc * Ff;
    const float* srcR = dre  + bbase;
    const float* srcI = dimg + bbase;

    // cooperative tile-load: 5120 elements (fl 8 x c 8 x tt CH), 20 per thread
    const unsigned tA = s2u(tileA);
    const unsigned tB = s2u(tileB);

    // ---- issue chunk 0 loads first (overlap with mask phase) ----
    {
        for (int k = 0; k < 20; k++) {
            int i  = tid + k*256;
            int fl = i & 7;
            int c  = (i >> 3) & 7;
            int tt = i >> 6;
            int fc = f0 + fl; if (fc >= Ff) fc = Ff-1;
            size_t so = (size_t)tt*(Cc*Ff) + c*Ff + fc;
            unsigned dst = tA + (unsigned)(((fl*CH + tt)*ROWP + c)*8);
            cpa4(dst,     srcR + so);
            cpa4(dst + 4, srcI + so);
        }
        cpa_commit();
    }

    // ---- phase 1: mask mean over c into smem ----
    for (int fl = 0; fl < 8; fl++) {
        int f = f0 + fl; if (f >= Ff) f = Ff-1;
        const float* ps = msk_s + ((size_t)(b*Ff + f)*Cc)*Tt;
        const float* pn = msk_n + ((size_t)(b*Ff + f)*Cc)*Tt;
        for (int t = tid; t < Tt; t += 256) {
            float ss = 0.f, sn = 0.f;
            #pragma unroll
            for (int c = 0; c < Cc; c++) {
                ss += fmaxf(ps[c*Tt + t], 1e-6f);
                sn += fmaxf(pn[c*Tt + t], 1e-6f);
            }
            smm[fl*Tt + t] = make_float2(ss*0.125f, sn*0.125f);
        }
    }
    __syncthreads();
    {   // per-f sums over t, one warp per f
        float as = 0.f, an = 0.f;
        for (int t = lane; t < Tt; t += 32) {
            float2 v = smm[warp*Tt + t]; as += v.x; an += v.y;
        }
        #pragma unroll
        for (int o = 16; o > 0; o >>= 1) {
            as += __shfl_down_sync(0xffffffffu, as, o);
            an += __shfl_down_sync(0xffffffffu, an, o);
        }
        if (lane == 0) { inv_s[warp] = 1.f/(as + 1e-15f); inv_n[warp] = 1.f/(an + 1e-15f); }
    }
    __syncthreads();
    for (int fl = 0; fl < 8; fl++) {
        float a = inv_s[fl], c2 = inv_n[fl];
        for (int t = tid; t < Tt; t += 256) {
            float2 v = smm[fl*Tt + t];
            smm[fl*Tt + t] = make_float2(v.x*a, v.y*c2);
        }
    }

    // ---- phase 2: double-buffered chunks, packed f32x2 accumulation ----
    const int fl   = warp;          // warp <-> f lane
    const int msel = lane & 1;
    const int ts   = lane >> 1;     // 0..15

    u64 acc[36];
    #pragma unroll
    for (int i = 0; i < 36; i++) acc[i] = 0ULL;

    for (int ch = 0; ch < NCH; ch++) {
        if (ch + 1 < NCH) {
            int t0n = (ch+1)*CH;
            unsigned tb = ((ch+1) & 1) ? tB : tA;
            for (int k = 0; k < 20; k++) {
                int i  = tid + k*256;
                int flv = i & 7;
                int c  = (i >> 3) & 7;
                int tt = i >> 6;
                int fc = f0 + flv; if (fc >= Ff) fc = Ff-1;
                size_t so = (size_t)(t0n + tt)*(Cc*Ff) + c*Ff + fc;
                unsigned dst = tb + (unsigned)(((flv*CH + tt)*ROWP + c)*8);
                cpa4(dst,     srcR + so);
                cpa4(dst + 4, srcI + so);
            }
            cpa_commit();
            asm volatile("cp.async.wait_group 1;");
        } else {
            asm volatile("cp.async.wait_group 0;");
        }
        __syncthreads();

        const float2* buf = (ch & 1) ? tileB : tileA;
        const int t0 = ch*CH;
        #pragma unroll
        for (int it = 0; it < CH/16; it++) {
            int tt = ts + 16*it;
            float2 m2 = smm[fl*Tt + t0 + tt];
            float m = msel ? m2.y : m2.x;
            const float2* row = buf + (fl*CH + tt)*ROWP;
            float xr[8], xi[8];
            u64 av[8], cv[8];
            #pragma unroll
            for (int c = 0; c < 8; c++) {
                float2 v = row[c];
                xr[c] = v.x; xi[c] = v.y;
                av[c] = pk2(v.x, v.y);     // (re, im)
                cv[c] = pk2(v.y, v.x);     // (im, re)
            }
            #pragma unroll
            for (int e = 0; e < 8; e++) {
                float bre = xr[e]*m, bie = xi[e]*m;
                u64 br = pk2(bre,  bre);
                u64 bi = pk2(bie, -bie);
                #pragma unroll
                for (int c = 0; c <= e; c++) {
                    int id = (e*(e+1))/2 + c;
                    // psd[c][e] += m * x_c * conj(x_e)
                    fma2(acc[id], av[c], br);   // re+=xr_c*bre, im+=xi_c*bre
                    fma2(acc[id], cv[c], bi);   // re+=xi_c*bie, im-=xr_c*bie
                }
            }
        }
        __syncthreads();
    }

    // ---- warp-shuffle reduction over ts (keep msel in bit 0) ----
    #pragma unroll
    for (int i = 0; i < 36; i++) {
        u64 v = acc[i];
        v = add2(v, __shfl_xor_sync(0xffffffffu, v, 16));
        v = add2(v, __shfl_xor_sync(0xffffffffu, v, 8));
        v = add2(v, __shfl_xor_sync(0xffffffffu, v, 4));
        v = add2(v, __shfl_xor_sync(0xffffffffu, v, 2));
        acc[i] = v;
    }

    float2* red = sm2;  // reuse mask region (dead now)
    if (lane < 2) {
        float2* dst = red + (fl*2 + msel)*36;
        #pragma unroll
        for (int i = 0; i < 36; i++) {
            float lo, hi; upk2(lo, hi, acc[i]);
            dst[i] = make_float2(lo, hi);
        }
    }
    __syncthreads();

    // expand Hermitian and write (8 fl x 2 mask x 64 entries)
    for (int idx = tid; idx < 1024; idx += 256) {
        int fl2 = idx >> 7;
        int rem = idx & 127;
        int mk  = rem >> 6;
        int ce  = rem & 63;
        int c   = ce >> 3, e = ce & 7;
        int ff  = f0 + fl2; if (ff >= Ff) continue;
        const float2* src = red + (fl2*2 + mk)*36;
        float2 v;
        if (c <= e) v = src[(e*(e+1))/2 + c];
        else { float2 u = src[(c*(c+1))/2 + e]; v = make_float2(u.x, -u.y); }
        float2* dstp = (mk == 0 ? g_psd_s : g_psd_n);
        dstp[(size_t)(b*Ff + ff)*64 + ce] = v;
    }
}

// ---------------- K2a: attention partial GEMV ----------------------------
// grid (9 chunks, 64 bc), block 320
__global__ void attn1_kernel(const float* __restrict__ mlp_w)
{
    __shared__ float feat[64];
    const int tid = threadIdx.x;
    const int bc  = blockIdx.y;
    const int b   = bc >> 3;
    const int c   = bc & 7;
    const int ch  = blockIdx.x;
    const int fbeg = ch*64;
    const int L = min(64, Ff - fbeg);

    if (tid < L) {
        int f = fbeg + tid;
        const float2* p = g_psd_s + (size_t)(b*Ff + f)*64 + c*8;
        float sr = 0.f, si = 0.f;
        #pragma unroll
        for (int e = 0; e < 8; e++) { float2 v = p[e]; sr += v.x; si += v.y; }
        float2 d = p[c]; sr -= d.x; si -= d.y;   // zero diagonal
        sr *= (1.f/7.f); si *= (1.f/7.f);
        feat[tid] = sqrtf(sr*sr + si*si);
    }
    __syncthreads();

    float acc = 0.f;
    const float* wp = mlp_w + (size_t)fbeg*Aa + tid;
    #pragma unroll 8
    for (int j = 0; j < L; j++) acc += feat[j] * wp[(size_t)j*Aa];
    g_part[(bc*9 + ch)*Aa + tid] = acc;
}

// ---------------- K2b: combine -> logits e[b,c] --------------------------
// grid 64, block 320
__global__ void attn2_kernel(const float* __restrict__ mlp_b,
                             const float* __restrict__ gvw,
                             const float* __restrict__ gvb)
{
    __shared__ float red[Aa];
    const int tid = threadIdx.x;
    const int bc  = blockIdx.x;
    float s = mlp_b[tid];
    #pragma unroll
    for (int ch = 0; ch < 9; ch++) s += g_part[(bc*9 + ch)*Aa + tid];
    red[tid] = tanhf(s) * gvw[tid];
    __syncthreads();
    if (tid < 160) red[tid] += red[tid+160]; __syncthreads();
    if (tid <  80) red[tid] += red[tid+ 80]; __syncthreads();
    if (tid <  40) red[tid] += red[tid+ 40]; __syncthreads();
    if (tid <  20) red[tid] += red[tid+ 20]; __syncthreads();
    if (tid <  10) red[tid] += red[tid+ 10]; __syncthreads();
    if (tid == 0) {
        float t = 0.f;
        #pragma unroll
        for (int i = 0; i < 10; i++) t += red[i];
        g_e[bc] = t + gvb[0];
    }
}

// ---------------- K3: MVDR solve + softmax + ws --------------------------
__global__ void solve_kernel()
{
    __shared__ float2 Ash[32][64];
    __shared__ float2 Ssh[32][64];
    const int tid = threadIdx.x;
    const int g = tid >> 3, r = tid & 7;
    int sys = blockIdx.x*32 + g;
    bool ok = sys < NSYS;
    int sc = ok ? sys : NSYS-1;
    int b = sc / Ff, f = sc - b*Ff;

    #pragma unroll
    for (int j = 0; j < 8; j++) {
        Ash[g][r*8+j] = g_psd_n[(size_t)sc*64 + r*8 + j];
        Ssh[g][r*8+j] = g_psd_s[(size_t)sc*64 + r*8 + j];
    }
    Ash[g][r*8+r].x += 1e-15f;

    float u[8];
    {
        float mx = -1e30f;
        #pragma unroll
        for (int j = 0; j < 8; j++) { u[j] = 2.f*g_e[b*8+j]; mx = fmaxf(mx, u[j]); }
        float s = 0.f;
        #pragma unroll
        for (int j = 0; j < 8; j++) { u[j] = expf(u[j]-mx); s += u[j]; }
        float is = 1.f/s;
        #pragma unroll
        for (int j = 0; j < 8; j++) u[j] *= is;
    }
    __syncwarp();

    for (int k = 0; k < 7; k++) {
        float2 ip = cinv(Ash[g][k*8+k]);
        if (r > k) {
            float2 fac = cmul(Ash[g][r*8+k], ip);
            #pragma unroll
            for (int j = 0; j < 8; j++)
                Ash[g][r*8+j] = csub(Ash[g][r*8+j], cmul(fac, Ash[g][k*8+j]));
            #pragma unroll
            for (int j = 0; j < 8; j++)
                Ssh[g][r*8+j] = csub(Ssh[g][r*8+j], cmul(fac, Ssh[g][k*8+j]));
        }
        __syncwarp();
    }
    for (int k = 7; k >= 0; k--) {
        if (r == k) {
            float2 ip = cinv(Ash[g][k*8+k]);
            #pragma unroll
            for (int j = 0; j < 8; j++)
                Ssh[g][k*8+j] = cmul(Ssh[g][k*8+j], ip);
        }
        __syncwarp();
        if (r < k) {
            float2 fac = Ash[g][r*8+k];
            #pragma unroll
            for (int j = 0; j < 8; j++)
                Ssh[g][r*8+j] = csub(Ssh[g][r*8+j], cmul(fac, Ssh[g][k*8+j]));
        }
        __syncwarp();
    }

    float2 tr = make_float2(1e-15f, 0.f);
    #pragma unroll
    for (int ci = 0; ci < 8; ci++) { float2 d = Ssh[g][ci*8+ci]; tr.x += d.x; tr.y += d.y; }
    float2 it = cinv(tr);
    float wr = 0.f, wi = 0.f;
    #pragma unroll
    for (int ci = 0; ci < 8; ci++) { float2 x = Ssh[g][r*8+ci]; wr += x.x*u[ci]; wi += x.y*u[ci]; }
    float2 w = cmul(make_float2(wr, wi), it);
    if (ok) g_wsc[(size_t)(b*8+r)*Ff + f] = make_float2(w.x, -w.y);   // store conj
}

// ---------------- K4: enhanced output ------------------------------------
// grid (100 t-tiles, 8 b), block 256; ws cached in smem (8x reuse)
__global__ void enh_kernel(const float* __restrict__ dre,
                           const float* __restrict__ dimg,
                           float2* __restrict__ out)
{
    __shared__ float2 wsh[8*Ff];
    const int tid = threadIdx.x;
    const int b  = blockIdx.y;
    const int t0 = blockIdx.x * 8;

    for (int i = tid; i < 8*Ff; i += 256)
        wsh[i] = g_wsc[(size_t)b*8*Ff + i];
    __syncthreads();

    for (int tt = 0; tt < 8; tt++) {
        size_t bt = (size_t)b*Tt + t0 + tt;
        const float* pr = dre  + bt*Cc*Ff;
        const float* pi = dimg + bt*Cc*Ff;
        for (int f = tid; f < Ff; f += 256) {
            float er = 0.f, ei = 0.f;
            #pragma unroll
            for (int c = 0; c < 8; c++) {
                float dr = pr[c*Ff + f];
                float di = pi[c*Ff + f];
                float2 w = wsh[c*Ff + f];   // = conj(ws)
                er += w.x*dr - w.y*di;
                ei += w.x*di + w.y*dr;
            }
            out[bt*Ff + f] = make_float2(er, ei);
        }
    }
}

// ---------------- launch --------------------------------------------------
extern "C" void kernel_launch(void* const* d_in, const int* in_sizes, int n_in,
                              void* d_out, int out_size)
{
    const float* dre   = (const float*)d_in[0];
    const float* dimg  = (const float*)d_in[1];
    const float* ms    = (const float*)d_in[2];
    const float* mn    = (const float*)d_in[3];
    const float* mlp_w = (const float*)d_in[4];
    const float* mlp_b = (const float*)d_in[5];
    const float* gvw   = (const float*)d_in[6];
    const float* gvb   = (const float*)d_in[7];
    (void)in_sizes; (void)n_in; (void)out_size;

    static int inited = 0;
    if (!inited) {
        cudaFuncSetAttribute(psd_kernel, cudaFuncAttributeMaxDynamicSharedMemorySize, DYN_SMEM);
        inited = 1;
    }

    psd_kernel<<<dim3((Ff+7)/8, Bb), 256, DYN_SMEM>>>(dre, dimg, ms, mn);
    attn1_kernel<<<dim3(9, 64), Aa>>>(mlp_w);
    attn2_kernel<<<64, Aa>>>(mlp_b, gvw, gvb);
    solve_kernel<<<(NSYS+31)/32, 256>>>();
    enh_kernel<<<dim3(Tt/8, Bb), 256>>>(dre, dimg, (float2*)d_out);
}

// round 4
// speedup vs baseline: 1.2087x; 1.2087x over previous
#include <cuda_runtime.h>

#define Bb 8
#define Tt 800
#define Cc 8
#define Ff 513
#define Aa 320
#define NSYS (Bb*Ff)
#define FB 57        // f per psd block (9*57 = 513 exactly)
#define NFB 9
#define TS 4         // t-chunks
#define TCH 200      // t per chunk
#define SUB 40       // t per smem stage
#define NSUB (TCH/SUB)

// ---------------- device scratch ----------------
__device__ float2 g_mt[NSYS*Tt];          // c-mean masks (ms, mn), 26MB
__device__ float2 g_inv[NSYS];            // 1/(sum+eps) per (b,f)
__device__ float2 g_part2[NSYS*2*TS*36];  // psd partials, 9.4MB
__device__ float2 g_psd_s[NSYS*64];
__device__ float2 g_psd_n[NSYS*64];
__device__ float  g_e[Bb*Cc];
__device__ float  g_attnpart[64*9*Aa];
__device__ float2 g_wsc[Bb*Cc*Ff];        // conj(ws), layout (b, c, f)

typedef unsigned long long u64;

__device__ __forceinline__ u64 pk2(float lo, float hi){
    u64 r; asm("mov.b64 %0, {%1, %2};" : "=l"(r) : "f"(lo), "f"(hi)); return r;
}
__device__ __forceinline__ void upk2(float &lo, float &hi, u64 v){
    asm("mov.b64 {%0, %1}, %2;" : "=f"(lo), "=f"(hi) : "l"(v));
}
__device__ __forceinline__ void fma2(u64 &d, u64 a, u64 b){
    asm("fma.rn.f32x2 %0, %1, %2, %0;" : "+l"(d) : "l"(a), "l"(b));
}
__device__ __forceinline__ float2 cmul(float2 a, float2 b){
    return make_float2(a.x*b.x - a.y*b.y, a.x*b.y + a.y*b.x);
}
__device__ __forceinline__ float2 csub(float2 a, float2 b){
    return make_float2(a.x - b.x, a.y - b.y);
}
__device__ __forceinline__ float2 cinv(float2 a){
    float d = 1.f/(a.x*a.x + a.y*a.y);
    return make_float2(a.x*d, -a.y*d);
}

// ---------------- K0: mask c-mean + normalization sums -------------------
// grid NSYS, block 256
__global__ void __launch_bounds__(256) mask_kernel(
    const float* __restrict__ msk_s, const float* __restrict__ msk_n)
{
    __shared__ float2 sred[8];
    const int sys = blockIdx.x;           // = b*Ff + f
    const int tid = threadIdx.x;
    const size_t base = (size_t)sys * Cc * Tt;

    float aS[4] = {0.f,0.f,0.f,0.f}, aN[4] = {0.f,0.f,0.f,0.f};
    #pragma unroll
    for (int c = 0; c < Cc; c++) {
        const float* ps = msk_s + base + c*Tt;
        const float* pn = msk_n + base + c*Tt;
        #pragma unroll
        for (int j = 0; j < 4; j++) {
            int t = tid + j*256;
            if (t < Tt) {
                aS[j] += fmaxf(ps[t], 1e-6f);
                aN[j] += fmaxf(pn[t], 1e-6f);
            }
        }
    }
    float sS = 0.f, sN = 0.f;
    #pragma unroll
    for (int j = 0; j < 4; j++) {
        int t = tid + j*256;
        if (t < Tt) {
            g_mt[(size_t)sys*Tt + t] = make_float2(aS[j]*0.125f, aN[j]*0.125f);
            sS += aS[j]; sN += aN[j];
        }
    }
    #pragma unroll
    for (int o = 16; o > 0; o >>= 1) {
        sS += __shfl_down_sync(0xffffffffu, sS, o);
        sN += __shfl_down_sync(0xffffffffu, sN, o);
    }
    if ((tid & 31) == 0) sred[tid >> 5] = make_float2(sS, sN);
    __syncthreads();
    if (tid == 0) {
        float ts_ = 0.f, tn = 0.f;
        #pragma unroll
        for (int i = 0; i < 8; i++) { ts_ += sred[i].x; tn += sred[i].y; }
        g_inv[sys] = make_float2(1.f/(ts_*0.125f + 1e-15f),
                                 1.f/(tn*0.125f + 1e-15f));
    }
}

// ---------------- K1: PSD partials ---------------------------------------
// grid (9, 8, 4), block 128: fi = tid&63 (f lane), msel = tid>>6
__global__ void __launch_bounds__(128) psd_kernel(
    const float* __restrict__ dre, const float* __restrict__ dimg)
{
    __shared__ float s_ms[FB*41];
    __shared__ float s_mn[FB*41];
    __shared__ float2 s_inv[FB];

    const int tid  = threadIdx.x;
    const int fi   = tid & 63;
    const int msel = tid >> 6;
    const int fblk = blockIdx.x;
    const int b    = blockIdx.y;
    const int ts   = blockIdx.z;
    const int f0   = fblk * FB;
    const int fiC  = fi < FB ? fi : FB-1;
    const int f    = f0 + fiC;
    const int t0   = ts * TCH;

    for (int i = tid; i < FB; i += 128) s_inv[i] = g_inv[b*Ff + f0 + i];

    u64 acc[36];
    #pragma unroll
    for (int i = 0; i < 36; i++) acc[i] = 0ULL;

    const size_t stepT = (size_t)Cc * Ff;
    const float* pr0 = dre  + ((size_t)b*Tt + t0) * stepT + f;
    const float* pi0 = dimg + ((size_t)b*Tt + t0) * stepT + f;

    for (int sub = 0; sub < NSUB; sub++) {
        __syncthreads();
        // stage normalized masks for this 40-t window
        const int tb = t0 + sub*SUB;
        for (int i = tid; i < FB*SUB; i += 128) {
            int fl = i / SUB, tt = i - fl*SUB;
            float2 mv = g_mt[(size_t)(b*Ff + f0 + fl)*Tt + tb + tt];
            float2 iv = s_inv[fl];
            s_ms[fl*41 + tt] = mv.x * iv.x;
            s_mn[fl*41 + tt] = mv.y * iv.y;
        }
        __syncthreads();

        const float* pr = pr0 + (size_t)sub*SUB*stepT;
        const float* pi = pi0 + (size_t)sub*SUB*stepT;
        const float* msh = (msel ? s_mn : s_ms) + fiC*41;

        #pragma unroll 2
        for (int tt = 0; tt < SUB; tt++) {
            float m = msh[tt];
            float xr[8], xi[8];
            u64 av[8], cv[8];
            #pragma unroll
            for (int c = 0; c < 8; c++) {
                xr[c] = pr[c*Ff];
                xi[c] = pi[c*Ff];
                av[c] = pk2(xr[c], xi[c]);
                cv[c] = pk2(xi[c], xr[c]);
            }
            #pragma unroll
            for (int e = 0; e < 8; e++) {
                float bre = xr[e]*m, bie = xi[e]*m;
                u64 br = pk2(bre,  bre);
                u64 bi = pk2(bie, -bie);
                #pragma unroll
                for (int c = 0; c <= e; c++) {
                    int id = (e*(e+1))/2 + c;
                    fma2(acc[id], av[c], br);   // re += xr_c*bre, im += xi_c*bre
                    fma2(acc[id], cv[c], bi);   // re += xi_c*bie, im -= xr_c*bie
                }
            }
            pr += stepT; pi += stepT;
        }
    }

    if (fi < FB) {
        float2* dst = g_part2 + ((size_t)((b*Ff + f)*2 + msel)*TS + ts)*36;
        #pragma unroll
        for (int i = 0; i < 36; i++) {
            float lo, hi; upk2(lo, hi, acc[i]);
            dst[i] = make_float2(lo, hi);
        }
    }
}

// ---------------- K1b: reduce partials + Hermitian expand ----------------
// grid NSYS, block 128
__global__ void reduce_kernel()
{
    const int sys = blockIdx.x;
    const int tid = threadIdx.x;
    const int msel = tid >> 6;
    const int ce = tid & 63;
    const int c = ce >> 3, e = ce & 7;
    const int hi = c > e ? c : e;
    const int lo = c > e ? e : c;
    const int id = (hi*(hi+1))/2 + lo;
    const float2* p = g_part2 + ((size_t)(sys*2 + msel)*TS)*36 + id;
    float2 v = p[0];
    float2 v1 = p[36], v2 = p[72], v3 = p[108];
    v.x += v1.x + v2.x + v3.x;
    v.y += v1.y + v2.y + v3.y;
    if (c > e) v.y = -v.y;
    (msel ? g_psd_n : g_psd_s)[(size_t)sys*64 + ce] = v;
}

// ---------------- K2a: attention partial GEMV ----------------------------
__global__ void attn1_kernel(const float* __restrict__ mlp_w)
{
    __shared__ float feat[64];
    const int tid = threadIdx.x;
    const int bc  = blockIdx.y;
    const int b   = bc >> 3;
    const int c   = bc & 7;
    const int fbeg = blockIdx.x * 64;
    const int L = min(64, Ff - fbeg);

    if (tid < L) {
        int f = fbeg + tid;
        const float2* p = g_psd_s + (size_t)(b*Ff + f)*64 + c*8;
        float sr = 0.f, si = 0.f;
        #pragma unroll
        for (int e = 0; e < 8; e++) { float2 v = p[e]; sr += v.x; si += v.y; }
        float2 d = p[c]; sr -= d.x; si -= d.y;
        sr *= (1.f/7.f); si *= (1.f/7.f);
        feat[tid] = sqrtf(sr*sr + si*si);
    }
    __syncthreads();

    float acc = 0.f;
    const float* wp = mlp_w + (size_t)fbeg*Aa + tid;
    #pragma unroll 8
    for (int j = 0; j < L; j++) acc += feat[j] * wp[(size_t)j*Aa];
    g_attnpart[(bc*9 + blockIdx.x)*Aa + tid] = acc;
}

__global__ void attn2_kernel(const float* __restrict__ mlp_b,
                             const float* __restrict__ gvw,
                             const float* __restrict__ gvb)
{
    __shared__ float red[Aa];
    const int tid = threadIdx.x;
    const int bc  = blockIdx.x;
    float s = mlp_b[tid];
    #pragma unroll
    for (int ch = 0; ch < 9; ch++) s += g_attnpart[(bc*9 + ch)*Aa + tid];
    red[tid] = tanhf(s) * gvw[tid];
    __syncthreads();
    if (tid < 160) red[tid] += red[tid+160]; __syncthreads();
    if (tid <  80) red[tid] += red[tid+ 80]; __syncthreads();
    if (tid <  40) red[tid] += red[tid+ 40]; __syncthreads();
    if (tid <  20) red[tid] += red[tid+ 20]; __syncthreads();
    if (tid <  10) red[tid] += red[tid+ 10]; __syncthreads();
    if (tid == 0) {
        float t = 0.f;
        #pragma unroll
        for (int i = 0; i < 10; i++) t += red[i];
        g_e[bc] = t + gvb[0];
    }
}

// ---------------- K3: MVDR solve, register rows + shfl broadcast ---------
// 8 lanes per system, 4 systems per warp, 32 systems per 256-thr block
__global__ void __launch_bounds__(256) solve_kernel()
{
    const unsigned FULL = 0xffffffffu;
    const int tid  = threadIdx.x;
    const int warp = tid >> 5, lane = tid & 31;
    const int g = lane >> 3, r = lane & 7;
    const int bl = lane & 24;               // base lane of this system

    int sys = blockIdx.x*32 + warp*4 + g;
    bool ok = sys < NSYS;
    int sc = ok ? sys : NSYS-1;
    int b = sc / Ff, f = sc - b*Ff;

    float2 A[8], S[8];
    #pragma unroll
    for (int j = 0; j < 8; j++) {
        A[j] = g_psd_n[(size_t)sc*64 + r*8 + j];
        S[j] = g_psd_s[(size_t)sc*64 + r*8 + j];
    }
    A[r].x += 1e-15f;

    float u[8];
    {
        float mx = -1e30f;
        #pragma unroll
        for (int j = 0; j < 8; j++) { u[j] = 2.f*g_e[b*8+j]; mx = fmaxf(mx, u[j]); }
        float s = 0.f;
        #pragma unroll
        for (int j = 0; j < 8; j++) { u[j] = expf(u[j]-mx); s += u[j]; }
        float is = 1.f/s;
        #pragma unroll
        for (int j = 0; j < 8; j++) u[j] *= is;
    }

    // forward elimination
    #pragma unroll
    for (int k = 0; k < 7; k++) {
        float2 pa[8], ps[8];
        #pragma unroll
        for (int j = 0; j < 8; j++) {
            pa[j].x = __shfl_sync(FULL, A[j].x, bl + k);
            pa[j].y = __shfl_sync(FULL, A[j].y, bl + k);
            ps[j].x = __shfl_sync(FULL, S[j].x, bl + k);
            ps[j].y = __shfl_sync(FULL, S[j].y, bl + k);
        }
        float2 ip = cinv(pa[k]);
        if (r > k) {
            float2 fac = cmul(A[k], ip);
            #pragma unroll
            for (int j = 0; j < 8; j++) {
                A[j] = csub(A[j], cmul(fac, pa[j]));
                S[j] = csub(S[j], cmul(fac, ps[j]));
            }
        }
    }
    // back substitution
    #pragma unroll
    for (int k = 7; k >= 0; k--) {
        if (r == k) {
            float2 ip = cinv(A[k]);
            #pragma unroll
            for (int j = 0; j < 8; j++) S[j] = cmul(S[j], ip);
        }
        float2 ps[8];
        #pragma unroll
        for (int j = 0; j < 8; j++) {
            ps[j].x = __shfl_sync(FULL, S[j].x, bl + k);
            ps[j].y = __shfl_sync(FULL, S[j].y, bl + k);
        }
        if (r < k) {
            float2 fac = A[k];
            #pragma unroll
            for (int j = 0; j < 8; j++) S[j] = csub(S[j], cmul(fac, ps[j]));
        }
    }

    // trace (diag j lives on lane bl+j)
    float2 tr = make_float2(1e-15f, 0.f);
    #pragma unroll
    for (int j = 0; j < 8; j++) {
        tr.x += __shfl_sync(FULL, S[j].x, bl + j);
        tr.y += __shfl_sync(FULL, S[j].y, bl + j);
    }
    float2 it = cinv(tr);
    float wr = 0.f, wi = 0.f;
    #pragma unroll
    for (int c = 0; c < 8; c++) { wr += S[c].x*u[c]; wi += S[c].y*u[c]; }
    float2 w = cmul(make_float2(wr, wi), it);
    if (ok) g_wsc[(size_t)(b*8+r)*Ff + f] = make_float2(w.x, -w.y);
}

// ---------------- K4: enhanced output ------------------------------------
__global__ void enh_kernel(const float* __restrict__ dre,
                           const float* __restrict__ dimg,
                           float2* __restrict__ out)
{
    __shared__ float2 wsh[8*Ff];
    const int tid = threadIdx.x;
    const int b  = blockIdx.y;
    const int t0 = blockIdx.x * 8;

    for (int i = tid; i < 8*Ff; i += 256)
        wsh[i] = g_wsc[(size_t)b*8*Ff + i];
    __syncthreads();

    for (int tt = 0; tt < 8; tt++) {
        size_t bt = (size_t)b*Tt + t0 + tt;
        const float* pr = dre  + bt*Cc*Ff;
        const float* pi = dimg + bt*Cc*Ff;
        for (int f = tid; f < Ff; f += 256) {
            float er = 0.f, ei = 0.f;
            #pragma unroll
            for (int c = 0; c < 8; c++) {
                float dr = pr[c*Ff + f];
                float di = pi[c*Ff + f];
                float2 w = wsh[c*Ff + f];
                er += w.x*dr - w.y*di;
                ei += w.x*di + w.y*dr;
            }
            out[bt*Ff + f] = make_float2(er, ei);
        }
    }
}

// ---------------- launch --------------------------------------------------
extern "C" void kernel_launch(void* const* d_in, const int* in_sizes, int n_in,
                              void* d_out, int out_size)
{
    const float* dre   = (const float*)d_in[0];
    const float* dimg  = (const float*)d_in[1];
    const float* ms    = (const float*)d_in[2];
    const float* mn    = (const float*)d_in[3];
    const float* mlp_w = (const float*)d_in[4];
    const float* mlp_b = (const float*)d_in[5];
    const float* gvw   = (const float*)d_in[6];
    const float* gvb   = (const float*)d_in[7];
    (void)in_sizes; (void)n_in; (void)out_size;

    mask_kernel<<<NSYS, 256>>>(ms, mn);
    psd_kernel<<<dim3(NFB, Bb, TS), 128>>>(dre, dimg);
    reduce_kernel<<<NSYS, 128>>>();
    attn1_kernel<<<dim3(9, 64), Aa>>>(mlp_w);
    attn2_kernel<<<64, Aa>>>(mlp_b, gvw, gvb);
    solve_kernel<<<(NSYS+31)/32, 256>>>();
    enh_kernel<<<dim3(Tt/8, Bb), 256>>>(dre, dimg, (float2*)d_out);
}

// round 5
// speedup vs baseline: 1.7907x; 1.4816x over previous
#include <cuda_runtime.h>

#define Bb 8
#define Tt 800
#define Cc 8
#define Ff 513
#define Aa 320
#define NSYS (Bb*Ff)
#define FB 57        // f per psd block (9*57 = 513 exactly)
#define NFB 9
#define TS 8         // t-chunks
#define TCH 100      // t per chunk
#define PSTRIDE 37   // 36 psd entries + 1 weight-sum, in float2 units

// ---------------- device scratch ----------------
__device__ float2 g_part2[NSYS*2*TS*PSTRIDE];  // psd partials + weight sums
__device__ float2 g_psd_s[NSYS*64];
__device__ float2 g_psd_n[NSYS*64];
__device__ float  g_e[Bb*Cc];
__device__ float  g_attnpart[64*9*Aa];
__device__ float2 g_wsc[Bb*Cc*Ff];             // conj(ws), layout (b, c, f)

typedef unsigned long long u64;

__device__ __forceinline__ u64 pk2(float lo, float hi){
    u64 r; asm("mov.b64 %0, {%1, %2};" : "=l"(r) : "f"(lo), "f"(hi)); return r;
}
__device__ __forceinline__ void upk2(float &lo, float &hi, u64 v){
    asm("mov.b64 {%0, %1}, %2;" : "=f"(lo), "=f"(hi) : "l"(v));
}
__device__ __forceinline__ void fma2(u64 &d, u64 a, u64 b){
    asm("fma.rn.f32x2 %0, %1, %2, %0;" : "+l"(d) : "l"(a), "l"(b));
}
__device__ __forceinline__ float2 cmul(float2 a, float2 b){
    return make_float2(a.x*b.x - a.y*b.y, a.x*b.y + a.y*b.x);
}
__device__ __forceinline__ float2 csub(float2 a, float2 b){
    return make_float2(a.x - b.x, a.y - b.y);
}
__device__ __forceinline__ float2 cinv(float2 a){
    float d = 1.f/(a.x*a.x + a.y*a.y);
    return make_float2(a.x*d, -a.y*d);
}

// accumulate one time step into 36 packed accumulators
__device__ __forceinline__ void psd_accum(const float* xr, const float* xi,
                                          float m, u64* acc, float& sumw)
{
    sumw += m;
    u64 av[8], cv[8];
    #pragma unroll
    for (int c = 0; c < 8; c++) {
        av[c] = pk2(xr[c], xi[c]);     // (re, im)
        cv[c] = pk2(xi[c], xr[c]);     // (im, re)
    }
    #pragma unroll
    for (int e = 0; e < 8; e++) {
        float bre = xr[e]*m, bie = xi[e]*m;
        u64 br = pk2(bre,  bre);
        u64 bi = pk2(bie, -bie);
        #pragma unroll
        for (int c = 0; c <= e; c++) {
            int id = (e*(e+1))/2 + c;
            fma2(acc[id], av[c], br);  // re += xr_c*bre, im += xi_c*bre
            fma2(acc[id], cv[c], bi);  // re += xi_c*bie, im -= xr_c*bie
        }
    }
}

// ---------------- K1: fused mask + PSD partials --------------------------
// grid (9, 8, 8), block 128: fi = tid&63 (f lane), msel = tid>>6
__global__ void __launch_bounds__(128) psd_kernel(
    const float* __restrict__ dre, const float* __restrict__ dimg,
    const float* __restrict__ msk_s, const float* __restrict__ msk_n)
{
    __shared__ float s_m[2][FB][TCH+1];   // [mask][f][t], row 101 -> conflict-free

    const int tid  = threadIdx.x;
    const int fi   = tid & 63;
    const int msel = tid >> 6;
    const int b    = blockIdx.y;
    const int f0   = blockIdx.x * FB;
    const int t0   = blockIdx.z * TCH;
    const int fiC  = fi < FB ? fi : FB-1;
    const int f    = f0 + fiC;

    // ---- stage c-mean of raw masks for this (57 f, 100 t) window ----
    for (int i = tid; i < FB*TCH; i += 128) {
        int fl = i / TCH, t = i - fl*TCH;
        const size_t mb = ((size_t)(b*Ff + f0 + fl)*Cc)*Tt + t0 + t;
        const float* ps = msk_s + mb;
        const float* pn = msk_n + mb;
        float ss = 0.f, sn = 0.f;
        #pragma unroll
        for (int c = 0; c < Cc; c++) {
            ss += fmaxf(ps[c*Tt], 1e-6f);
            sn += fmaxf(pn[c*Tt], 1e-6f);
        }
        s_m[0][fl][t] = ss * 0.125f;
        s_m[1][fl][t] = sn * 0.125f;
    }
    __syncthreads();

    const float* msh = &s_m[msel][fiC][0];
    const size_t stepT = (size_t)Cc * Ff;
    const float* pr = dre  + ((size_t)b*Tt + t0)*stepT + f;
    const float* pi = dimg + ((size_t)b*Tt + t0)*stepT + f;

    u64 acc[36];
    #pragma unroll
    for (int i = 0; i < 36; i++) acc[i] = 0ULL;
    float sumw = 0.f;

    // register double-buffer: prefetch t+1 while accumulating t
    float xr0[8], xi0[8], xr1[8], xi1[8];
    #pragma unroll
    for (int c = 0; c < 8; c++) { xr0[c] = pr[c*Ff]; xi0[c] = pi[c*Ff]; }

    #pragma unroll 1
    for (int tt = 0; tt < TCH; tt += 2) {
        const float* prA = pr + (size_t)(tt+1)*stepT;
        const float* piA = pi + (size_t)(tt+1)*stepT;
        #pragma unroll
        for (int c = 0; c < 8; c++) { xr1[c] = prA[c*Ff]; xi1[c] = piA[c*Ff]; }
        psd_accum(xr0, xi0, msh[tt], acc, sumw);
        if (tt + 2 < TCH) {
            const float* prB = pr + (size_t)(tt+2)*stepT;
            const float* piB = pi + (size_t)(tt+2)*stepT;
            #pragma unroll
            for (int c = 0; c < 8; c++) { xr0[c] = prB[c*Ff]; xi0[c] = piB[c*Ff]; }
        }
        psd_accum(xr1, xi1, msh[tt+1], acc, sumw);
    }

    if (fi < FB) {
        float2* dst = g_part2 +
            ((size_t)((b*Ff + f)*2 + msel)*TS + blockIdx.z)*PSTRIDE;
        #pragma unroll
        for (int i = 0; i < 36; i++) {
            float lo, hi; upk2(lo, hi, acc[i]);
            dst[i] = make_float2(lo, hi);
        }
        dst[36] = make_float2(sumw, 0.f);
    }
}

// ---------------- K1b: reduce partials, normalize, Hermitian expand ------
// grid NSYS, block 128: msel = tid>>6, ce = tid&63
__global__ void reduce_kernel()
{
    const int sys = blockIdx.x;
    const int tid = threadIdx.x;
    const int msel = tid >> 6;
    const int ce = tid & 63;
    const int c = ce >> 3, e = ce & 7;
    const int hi = c > e ? c : e;
    const int lo = c > e ? e : c;
    const int id = (hi*(hi+1))/2 + lo;

    const float2* base = g_part2 + ((size_t)(sys*2 + msel)*TS)*PSTRIDE;
    float2 v = make_float2(0.f, 0.f);
    float sw = 0.f;
    #pragma unroll
    for (int ts = 0; ts < TS; ts++) {
        float2 p = base[ts*PSTRIDE + id];
        v.x += p.x; v.y += p.y;
        sw  += base[ts*PSTRIDE + 36].x;        // warp-uniform -> broadcast
    }
    float inv = 1.f/(sw + 1e-15f);
    v.x *= inv; v.y *= inv;
    if (c > e) v.y = -v.y;
    (msel ? g_psd_n : g_psd_s)[(size_t)sys*64 + ce] = v;
}

// ---------------- K2a: attention partial GEMV ----------------------------
__global__ void attn1_kernel(const float* __restrict__ mlp_w)
{
    __shared__ float feat[64];
    const int tid = threadIdx.x;
    const int bc  = blockIdx.y;
    const int b   = bc >> 3;
    const int c   = bc & 7;
    const int fbeg = blockIdx.x * 64;
    const int L = min(64, Ff - fbeg);

    if (tid < L) {
        int f = fbeg + tid;
        const float2* p = g_psd_s + (size_t)(b*Ff + f)*64 + c*8;
        float sr = 0.f, si = 0.f;
        #pragma unroll
        for (int e = 0; e < 8; e++) { float2 v = p[e]; sr += v.x; si += v.y; }
        float2 d = p[c]; sr -= d.x; si -= d.y;
        sr *= (1.f/7.f); si *= (1.f/7.f);
        feat[tid] = sqrtf(sr*sr + si*si);
    }
    __syncthreads();

    float a0 = 0.f, a1 = 0.f;
    const float* wp = mlp_w + (size_t)fbeg*Aa + tid;
    int j = 0;
    #pragma unroll 8
    for (; j + 1 < L; j += 2) {
        a0 += feat[j]   * wp[(size_t)j*Aa];
        a1 += feat[j+1] * wp[(size_t)(j+1)*Aa];
    }
    if (j < L) a0 += feat[j] * wp[(size_t)j*Aa];
    g_attnpart[(bc*9 + blockIdx.x)*Aa + tid] = a0 + a1;
}

__global__ void attn2_kernel(const float* __restrict__ mlp_b,
                             const float* __restrict__ gvw,
                             const float* __restrict__ gvb)
{
    __shared__ float red[Aa];
    const int tid = threadIdx.x;
    const int bc  = blockIdx.x;
    float s = mlp_b[tid];
    #pragma unroll
    for (int ch = 0; ch < 9; ch++) s += g_attnpart[(bc*9 + ch)*Aa + tid];
    red[tid] = tanhf(s) * gvw[tid];
    __syncthreads();
    if (tid < 160) red[tid] += red[tid+160]; __syncthreads();
    if (tid <  80) red[tid] += red[tid+ 80]; __syncthreads();
    if (tid <  40) red[tid] += red[tid+ 40]; __syncthreads();
    if (tid <  20) red[tid] += red[tid+ 20]; __syncthreads();
    if (tid <  10) red[tid] += red[tid+ 10]; __syncthreads();
    if (tid == 0) {
        float t = 0.f;
        #pragma unroll
        for (int i = 0; i < 10; i++) t += red[i];
        g_e[bc] = t + gvb[0];
    }
}

// ---------------- K3: MVDR solve, register rows + shfl broadcast ---------
__global__ void __launch_bounds__(256) solve_kernel()
{
    const unsigned FULL = 0xffffffffu;
    const int tid  = threadIdx.x;
    const int warp = tid >> 5, lane = tid & 31;
    const int g = lane >> 3, r = lane & 7;
    const int bl = lane & 24;

    int sys = blockIdx.x*32 + warp*4 + g;
    bool ok = sys < NSYS;
    int sc = ok ? sys : NSYS-1;
    int b = sc / Ff, f = sc - b*Ff;

    float2 A[8], S[8];
    #pragma unroll
    for (int j = 0; j < 8; j++) {
        A[j] = g_psd_n[(size_t)sc*64 + r*8 + j];
        S[j] = g_psd_s[(size_t)sc*64 + r*8 + j];
    }
    A[r].x += 1e-15f;

    float u[8];
    {
        float mx = -1e30f;
        #pragma unroll
        for (int j = 0; j < 8; j++) { u[j] = 2.f*g_e[b*8+j]; mx = fmaxf(mx, u[j]); }
        float s = 0.f;
        #pragma unroll
        for (int j = 0; j < 8; j++) { u[j] = expf(u[j]-mx); s += u[j]; }
        float is = 1.f/s;
        #pragma unroll
        for (int j = 0; j < 8; j++) u[j] *= is;
    }

    #pragma unroll
    for (int k = 0; k < 7; k++) {
        float2 pa[8], ps[8];
        #pragma unroll
        for (int j = 0; j < 8; j++) {
            pa[j].x = __shfl_sync(FULL, A[j].x, bl + k);
            pa[j].y = __shfl_sync(FULL, A[j].y, bl + k);
            ps[j].x = __shfl_sync(FULL, S[j].x, bl + k);
            ps[j].y = __shfl_sync(FULL, S[j].y, bl + k);
        }
        float2 ip = cinv(pa[k]);
        if (r > k) {
            float2 fac = cmul(A[k], ip);
            #pragma unroll
            for (int j = 0; j < 8; j++) {
                A[j] = csub(A[j], cmul(fac, pa[j]));
                S[j] = csub(S[j], cmul(fac, ps[j]));
            }
        }
    }
    #pragma unroll
    for (int k = 7; k >= 0; k--) {
        if (r == k) {
            float2 ip = cinv(A[k]);
            #pragma unroll
            for (int j = 0; j < 8; j++) S[j] = cmul(S[j], ip);
        }
        float2 ps[8];
        #pragma unroll
        for (int j = 0; j < 8; j++) {
            ps[j].x = __shfl_sync(FULL, S[j].x, bl + k);
            ps[j].y = __shfl_sync(FULL, S[j].y, bl + k);
        }
        if (r < k) {
            float2 fac = A[k];
            #pragma unroll
            for (int j = 0; j < 8; j++) S[j] = csub(S[j], cmul(fac, ps[j]));
        }
    }

    float2 tr = make_float2(1e-15f, 0.f);
    #pragma unroll
    for (int j = 0; j < 8; j++) {
        tr.x += __shfl_sync(FULL, S[j].x, bl + j);
        tr.y += __shfl_sync(FULL, S[j].y, bl + j);
    }
    float2 it = cinv(tr);
    float wr = 0.f, wi = 0.f;
    #pragma unroll
    for (int c = 0; c < 8; c++) { wr += S[c].x*u[c]; wi += S[c].y*u[c]; }
    float2 w = cmul(make_float2(wr, wi), it);
    if (ok) g_wsc[(size_t)(b*8+r)*Ff + f] = make_float2(w.x, -w.y);
}

// ---------------- K4: enhanced output ------------------------------------
__global__ void enh_kernel(const float* __restrict__ dre,
                           const float* __restrict__ dimg,
                           float2* __restrict__ out)
{
    __shared__ float2 wsh[8*Ff];
    const int tid = threadIdx.x;
    const int b  = blockIdx.y;
    const int t0 = blockIdx.x * 8;

    for (int i = tid; i < 8*Ff; i += 256)
        wsh[i] = g_wsc[(size_t)b*8*Ff + i];
    __syncthreads();

    for (int tt = 0; tt < 8; tt++) {
        size_t bt = (size_t)b*Tt + t0 + tt;
        const float* pr = dre  + bt*Cc*Ff;
        const float* pi = dimg + bt*Cc*Ff;
        for (int f = tid; f < Ff; f += 256) {
            float er = 0.f, ei = 0.f;
            #pragma unroll
            for (int c = 0; c < 8; c++) {
                float dr = pr[c*Ff + f];
                float di = pi[c*Ff + f];
                float2 w = wsh[c*Ff + f];
                er += w.x*dr - w.y*di;
                ei += w.x*di + w.y*dr;
            }
            out[bt*Ff + f] = make_float2(er, ei);
        }
    }
}

// ---------------- launch --------------------------------------------------
extern "C" void kernel_launch(void* const* d_in, const int* in_sizes, int n_in,
                              void* d_out, int out_size)
{
    const float* dre   = (const float*)d_in[0];
    const float* dimg  = (const float*)d_in[1];
    const float* ms    = (const float*)d_in[2];
    const float* mn    = (const float*)d_in[3];
    const float* mlp_w = (const float*)d_in[4];
    const float* mlp_b = (const float*)d_in[5];
    const float* gvw   = (const float*)d_in[6];
    const float* gvb   = (const float*)d_in[7];
    (void)in_sizes; (void)n_in; (void)out_size;

    psd_kernel<<<dim3(NFB, Bb, TS), 128>>>(dre, dimg, ms, mn);
    reduce_kernel<<<NSYS, 128>>>();
    attn1_kernel<<<dim3(9, 64), Aa>>>(mlp_w);
    attn2_kernel<<<64, Aa>>>(mlp_b, gvw, gvb);
    solve_kernel<<<(NSYS+31)/32, 256>>>();
    enh_kernel<<<dim3(Tt/8, Bb), 256>>>(dre, dimg, (float2*)d_out);
}